// round 1
// baseline (speedup 1.0000x reference)
#include <cuda_runtime.h>
#include <cuda_bf16.h>
#include <cstdint>

// ---------------------------------------------------------------------------
// PPEG: out = dwconv7(x) + x + dwconv5(x) + dwconv3(x)  (depthwise, per-channel)
// Folded into ONE 7x7x7 depthwise conv per channel + combined bias.
//
// x layout  (per channel c): volume[d][h][w], d=16, h=64, w=64 (w contiguous)
// out layout(per channel c): [h][w][d] with d contiguous (stride-1)
// ---------------------------------------------------------------------------

#define NCH   512
#define DD    16
#define HH    64
#define WW    64
#define VOL   (DD*HH*WW)      // 65536 per channel

#define WSTRIDE 352           // per-channel slot in g_wcomb (343 taps + bias, padded)
__device__ float g_wcomb[NCH * WSTRIDE];

// -------------------- weight folding --------------------
__global__ void fold_weights_kernel(const float* __restrict__ w7,
                                    const float* __restrict__ b7,
                                    const float* __restrict__ w5,
                                    const float* __restrict__ b5,
                                    const float* __restrict__ w3,
                                    const float* __restrict__ b3) {
    int c = blockIdx.x;
    for (int t = threadIdx.x; t < 343; t += blockDim.x) {
        int dd = t / 49;
        int r  = t % 49;
        int dh = r / 7;
        int dw = r % 7;
        float v = w7[c * 343 + t];
        if (dd >= 1 && dd <= 5 && dh >= 1 && dh <= 5 && dw >= 1 && dw <= 5)
            v += w5[c * 125 + (dd - 1) * 25 + (dh - 1) * 5 + (dw - 1)];
        if (dd >= 2 && dd <= 4 && dh >= 2 && dh <= 4 && dw >= 2 && dw <= 4)
            v += w3[c * 27 + (dd - 2) * 9 + (dh - 2) * 3 + (dw - 2)];
        if (t == 171) v += 1.0f;   // identity: center tap (3,3,3) -> 3*49+3*7+3
        g_wcomb[c * WSTRIDE + t] = v;
    }
    if (threadIdx.x == 0)
        g_wcomb[c * WSTRIDE + 343] = b7[c] + b5[c] + b3[c];
}

// -------------------- main conv --------------------
// CTA: one channel, 4 consecutive h rows, full W, full D.
// Thread: one (h,w) -> 16 d-outputs (contiguous in output).
// Smem tile: [sd=22][sh=10][sw=70]  (halo 3 on every side, zero-padded)
#define SM_D 22
#define SM_H 10
#define SM_W 70
#define SM_ELEMS (SM_D * SM_H * SM_W)   // 15400

__global__ __launch_bounds__(256)
void ppeg_conv_kernel(const float* __restrict__ x, float* __restrict__ out) {
    extern __shared__ float smem[];
    float* sx  = smem;                // input tile
    float* swt = smem + SM_ELEMS;     // 344 weights (343 taps + bias)

    const int c   = blockIdx.y;
    const int h0  = blockIdx.x * 4;
    const int tid = threadIdx.x;

    const float* __restrict__ xc = x + (size_t)c * VOL;

    // load folded weights for this channel
    for (int i = tid; i < 344; i += 256)
        swt[i] = g_wcomb[c * WSTRIDE + i];

    // load input tile with halo (zero outside volume)
    for (int i = tid; i < SM_ELEMS; i += 256) {
        int sd = i / (SM_H * SM_W);
        int r  = i % (SM_H * SM_W);
        int sh = r / SM_W;
        int sw = r % SM_W;
        int gd = sd - 3;
        int gh = h0 + sh - 3;
        int gw = sw - 3;
        float v = 0.0f;
        if ((unsigned)gd < (unsigned)DD &&
            (unsigned)gh < (unsigned)HH &&
            (unsigned)gw < (unsigned)WW)
            v = xc[(gd * HH + gh) * WW + gw];
        sx[i] = v;
    }
    __syncthreads();

    const int w  = tid & 63;   // 0..63  (warp = 32 consecutive w -> conflict-free LDS)
    const int hl = tid >> 6;   // 0..3

    const float bias = swt[343];
    float acc[16];
#pragma unroll
    for (int o = 0; o < 16; ++o) acc[o] = bias;

#pragma unroll 1
    for (int dh = 0; dh < 7; ++dh) {
        const float* colbase = sx + (hl + dh) * SM_W + w;
#pragma unroll
        for (int dw = 0; dw < 7; ++dw) {
            // d-column at (h = h0+hl+dh-3, w = w+dw-3), 22 deep
            float z[SM_D];
#pragma unroll
            for (int sd = 0; sd < SM_D; ++sd)
                z[sd] = colbase[sd * (SM_H * SM_W) + dw];
#pragma unroll
            for (int dd = 0; dd < 7; ++dd) {
                const float wv = swt[(dd * 7 + dh) * 7 + dw];
#pragma unroll
                for (int o = 0; o < 16; ++o)
                    acc[o] = fmaf(z[o + dd], wv, acc[o]);
            }
        }
    }

    // out[c][(h*64+w)*16 + d] : 16 contiguous floats per thread
    float4* op = (float4*)(out + (size_t)c * VOL + ((size_t)(h0 + hl) * WW + w) * 16);
    op[0] = make_float4(acc[0],  acc[1],  acc[2],  acc[3]);
    op[1] = make_float4(acc[4],  acc[5],  acc[6],  acc[7]);
    op[2] = make_float4(acc[8],  acc[9],  acc[10], acc[11]);
    op[3] = make_float4(acc[12], acc[13], acc[14], acc[15]);
}

// -------------------- launch --------------------
extern "C" void kernel_launch(void* const* d_in, const int* in_sizes, int n_in,
                              void* d_out, int out_size) {
    const float* x  = (const float*)d_in[0];
    const float* w7 = (const float*)d_in[1];
    const float* b7 = (const float*)d_in[2];
    const float* w5 = (const float*)d_in[3];
    const float* b5 = (const float*)d_in[4];
    const float* w3 = (const float*)d_in[5];
    const float* b3 = (const float*)d_in[6];
    float* out = (float*)d_out;

    fold_weights_kernel<<<NCH, 256>>>(w7, b7, w5, b5, w3, b3);

    const int smem_bytes = (SM_ELEMS + 344) * sizeof(float);  // ~63 KB
    static bool attr_set = false;  // idempotent host-side attribute (not a guard on work)
    if (!attr_set) {
        cudaFuncSetAttribute(ppeg_conv_kernel,
                             cudaFuncAttributeMaxDynamicSharedMemorySize, smem_bytes);
        attr_set = true;
    }

    dim3 grid(HH / 4, NCH);   // 16 h-tiles x 512 channels
    ppeg_conv_kernel<<<grid, 256, smem_bytes>>>(x, out);
}